// round 2
// baseline (speedup 1.0000x reference)
#include <cuda_runtime.h>

// GCBFSafetyLayer — analytical reduction (see R1): L_g_h == 0 identically
// (dh_dx velocity-half is zero, g position-half is zero), so the projection
// never modifies u and safe_action == raw_action bit-exactly.
//
// Kernel = identity copy of d_in[3] (256*128*2 floats = 256 KB) into d_out.
//
// R2: minimal issue path. 16384 float4 = 128 blocks x 128 threads exactly,
// so no bounds check and no size parameter: body is LDG.128 / STG.128 / EXIT.
// 128 single-CTA blocks spread across ~128 SMs (wave-1 deterministic
// placement), minimizing per-SM tail. This is launch-overhead bound; the
// memory work (~0.35us of L2-warm latency) is fully hidden under dispatch.

__global__ void __launch_bounds__(128, 1)
gcbf_identity_copy_kernel(const float4* __restrict__ src,
                          float4* __restrict__ dst) {
    unsigned i = blockIdx.x * 128u + threadIdx.x;
    dst[i] = src[i];
}

extern "C" void kernel_launch(void* const* d_in, const int* in_sizes, int n_in,
                              void* d_out, int out_size) {
    // Inputs (metadata order): positions, velocities, obstacles, raw_action
    const float4* raw_action = (const float4*)d_in[3];
    float4* out = (float4*)d_out;

    // out_size = 65536 floats = 16384 float4 = 128 * 128 exactly.
    gcbf_identity_copy_kernel<<<128, 128>>>(raw_action, out);
}

// round 3
// speedup vs baseline: 1.2098x; 1.2098x over previous
#include <cuda_runtime.h>

// GCBFSafetyLayer — analytical reduction (see R1): L_g_h == 0 identically
// (dh_dx velocity-half is zero, g position-half is zero), so the projection
// loop's update is gated by ||a||^2 > 1e-6 which is never true, u is never
// modified, and safe_action == raw_action bit-exactly.
//
// Kernel = identity copy of d_in[3] (256*128*2 floats = 256 KB) into d_out.
//
// R3: R2 showed block shape dominates (128-thread blocks regressed: only 4
// warps/SM of latency hiding). Revert to 256-thread blocks and halve CTA
// count by giving each thread 2 independent float4s (MLP=2, both LDG.128
// issued before the first STG). 32 CTAs x 256 thr x 2 float4 = 16384 exact,
// no bounds checks.

__global__ void __launch_bounds__(256, 1)
gcbf_identity_copy_kernel(const float4* __restrict__ src,
                          float4* __restrict__ dst) {
    // Each CTA owns a contiguous 512-float4 chunk; thread t handles
    // elements t and t+256 within the chunk (coalesced both times).
    unsigned base = blockIdx.x * 512u + threadIdx.x;
    float4 a = src[base];
    float4 b = src[base + 256u];
    dst[base] = a;
    dst[base + 256u] = b;
}

extern "C" void kernel_launch(void* const* d_in, const int* in_sizes, int n_in,
                              void* d_out, int out_size) {
    // Inputs (metadata order): positions, velocities, obstacles, raw_action
    const float4* raw_action = (const float4*)d_in[3];
    float4* out = (float4*)d_out;

    // out_size = 65536 floats = 16384 float4 = 32 * 256 * 2 exactly.
    gcbf_identity_copy_kernel<<<32, 256>>>(raw_action, out);
}